// round 1
// baseline (speedup 1.0000x reference)
#include <cuda_runtime.h>
#include <cstdint>
#include <cfloat>

// SQuant 4-bit adaptive rounding, fused single kernel.
// weight: (1024, 1024, 3, 3) fp32. One block per output channel (row of 9216).
//
// Per row: minmax -> scale/zp -> per-9-element group flip pass (SQuant-K) ->
// row-level flip pass over the per-group boundary candidates (SQuant-C) ->
// clip + dequantize.

#define NROWS    1024
#define ROWLEN   9216
#define NTHREADS 1024

// shared layout (dynamic):
//   [0,     36864)  s_w   : row of 9216 floats   (dead after pass 1; first 8KB
//                            reused as s_key for the pass-2 bitonic sort)
//   [36864, 46080)  s_r   : 9216 int8 rounded values
//   [46080, 46336)  s_red : 64 floats reduction scratch
//   [46336, 46352)  s_bc  : broadcast (scale, zp, e2)
#define SMEM_BYTES 46352

__device__ __forceinline__ float warpSum(float v) {
#pragma unroll
    for (int o = 16; o; o >>= 1) v += __shfl_xor_sync(0xffffffffu, v, o);
    return v;
}
__device__ __forceinline__ float warpMaxR(float v) {
#pragma unroll
    for (int o = 16; o; o >>= 1) v = fmaxf(v, __shfl_xor_sync(0xffffffffu, v, o));
    return v;
}
__device__ __forceinline__ float warpMinR(float v) {
#pragma unroll
    for (int o = 16; o; o >>= 1) v = fminf(v, __shfl_xor_sync(0xffffffffu, v, o));
    return v;
}

__global__ void __launch_bounds__(NTHREADS, 1)
squant_kernel(const float* __restrict__ w, float* __restrict__ out)
{
    extern __shared__ unsigned char smem[];
    float* s_w = (float*)smem;                                   // 36864 B
    unsigned long long* s_key = (unsigned long long*)smem;       // aliases s_w (8192 B)
    signed char* s_r = (signed char*)(smem + 36864);             // 9216 B
    float* s_red = (float*)(smem + 46080);                       // 64 floats
    float* s_bc  = (float*)(smem + 46336);                       // 4 floats

    const int row  = blockIdx.x;
    const int tid  = threadIdx.x;
    const int lane = tid & 31;
    const int wid  = tid >> 5;
    const float* __restrict__ wr = w + (size_t)row * ROWLEN;

    // ---- load row + min/max ----
    float vmax = -FLT_MAX, vmin = FLT_MAX;
#pragma unroll
    for (int i = tid; i < ROWLEN; i += NTHREADS) {
        float v = wr[i];
        s_w[i] = v;
        vmax = fmaxf(vmax, v);
        vmin = fminf(vmin, v);
    }
    vmax = warpMaxR(vmax);
    vmin = warpMinR(vmin);
    if (lane == 0) { s_red[wid] = vmax; s_red[32 + wid] = vmin; }
    __syncthreads();
    if (wid == 0) {
        float m = warpMaxR(s_red[lane]);
        float n = warpMinR(s_red[32 + lane]);
        if (lane == 0) {
            float sc = 15.0f / fmaxf(m - n, 1e-8f);
            s_bc[0] = sc;
            s_bc[1] = rintf(sc * n) + 8.0f;   // zero point
        }
    }
    __syncthreads();
    const float scale = s_bc[0];
    const float zp    = s_bc[1];

    // ---- pass 1: SQuant-K over this thread's 9-element kernel group ----
    const int base = tid * 9;
    float rv[9], ev[9];           // constant-indexed only -> stay in registers
    unsigned cu = 0, cd = 0;
    float e = 0.f;
#pragma unroll
    for (int j = 0; j < 9; j++) {
        float qq = scale * s_w[base + j] - zp;
        float rr = rintf(qq);
        float ee = rr - qq;
        rv[j] = rr; ev[j] = ee;
        if (ee < 0.f && qq <  7.f) cu |= (1u << j);
        if (ee > 0.f && qq > -8.f) cd |= (1u << j);
        e += ee;
    }
    const bool is_up = (e < 0.f);
    int nflip = (int)rintf(fabsf(e));     // mathematically <= 4
    if (nflip > 8) nflip = 8;
    const unsigned cand = is_up ? cu : cd;

    // greedy selection: top-(nflip+1) by (pri desc, index asc).
    // pri_j = |ev_j| if candidate else 0 (matches up_pri/-err and dn_pri/err).
    unsigned sel = 0;
    int ni = 0, li = -1;
    for (int p = 0; p <= nflip; p++) {
        float bp = -1.f; int bj = 0;
#pragma unroll
        for (int j = 0; j < 9; j++) {
            float pj = ((cand >> j) & 1u) ? fabsf(ev[j]) : 0.f;
            if (!((sel >> j) & 1u) && pj > bp) { bp = pj; bj = j; }
        }
        sel |= (1u << bj);
        if (p == nflip) ni = bj;
        else if (p == nflip - 1) li = bj;
    }

    // apply flips (all selected except ni), accumulate residual error
    const float dir = is_up ? 1.f : -1.f;
    const unsigned flipm = sel & ~(1u << ni);
    float er = 0.f;
#pragma unroll
    for (int j = 0; j < 9; j++) {
        float nr = rv[j], ne = ev[j];
        if ((flipm >> j) & 1u) {
            if ((cand >> j) & 1u) { nr += dir; ne += dir; }
            else                  { ne = 0.f; }   // flipping a non-candidate zeroes err
        }
        er += ne;
        s_r[base + j] = (signed char)__float2int_rn(nr);
    }

    // pull rv/ev at ni and li without dynamic indexing (keep arrays in regs)
    float evNi = 0.f, rvNi = 0.f, evLi = 0.f, rvLi = 0.f;
#pragma unroll
    for (int j = 0; j < 9; j++) {
        if (j == ni) { evNi = ev[j]; rvNi = rv[j]; }
        if (j == li) { evLi = ev[j]; rvLi = rv[j]; }
    }
    const bool candNi = (cand >> ni) & 1u;
    const bool candLi = (li >= 0) && ((cand >> li) & 1u);

    // boundary-candidate handoff for pass 2
    const float priNi = candNi ? fabsf(evNi) : 0.f;               // next_pri
    const int   valNi = (int)rvNi + (candNi ? (is_up ? 1 : -1) : 0);
    float priLi; int valLi, idxLi;
    if (li >= 0) {                                                // revert-last candidate
        priLi = 1.f - (candLi ? fabsf(evLi) : 0.f);
        valLi = (int)rvLi;                                        // pre-flip value
        idxLi = base + li;
    } else {                                                      // no flips: harmless pri-0 dummy
        priLi = 0.f; valLi = (int)rvNi; idxLi = base + ni;
    }

    float upP, dnP; int upI, dnI, upV, dnV;
    if (is_up) { upP = priNi; upI = base + ni; upV = valNi;
                 dnP = priLi; dnI = idxLi;    dnV = valLi; }
    else       { dnP = priNi; dnI = base + ni; dnV = valNi;
                 upP = priLi; upI = idxLi;    upV = valLi; }

    // ---- row residual-error reduction -> pass-2 flip budget ----
    float s = warpSum(er);
    if (lane == 0) s_red[wid] = s;
    __syncthreads();
    if (wid == 0) {
        float t2 = warpSum(s_red[lane]);
        if (lane == 0) s_bc[2] = t2;
    }
    __syncthreads();
    const float e2  = s_bc[2];
    const bool  up2 = (e2 < 0.f);
    int nflip2 = (int)rintf(fabsf(e2));
    if (nflip2 > NTHREADS) nflip2 = NTHREADS;

    // pack this group's candidate (in chosen direction) into a sortable key:
    //   [pri float bits : 32][~idx : 14 (asc idx preferred)][val+64 : 8]
    const float P = up2 ? upP : dnP;
    const int   I = up2 ? upI : dnI;
    const int   V = up2 ? upV : dnV;
    unsigned long long key =
          ((unsigned long long)__float_as_uint(P) << 32)
        | ((unsigned long long)(unsigned)(0x3FFF - I) << 8)
        | (unsigned long long)(unsigned)(V + 64);
    // all s_w reads completed before the e2 reduction barriers -> safe to alias
    s_key[tid] = key;
    __syncthreads();

    // ---- bitonic sort, descending (stable via ~idx in key; keys unique) ----
#pragma unroll 1
    for (int k = 2; k <= NTHREADS; k <<= 1) {
#pragma unroll 1
        for (int j = k >> 1; j > 0; j >>= 1) {
            int ixj = tid ^ j;
            if (ixj > tid) {
                unsigned long long a = s_key[tid];
                unsigned long long b = s_key[ixj];
                bool desc = ((tid & k) == 0);
                if ((a < b) == desc) { s_key[tid] = b; s_key[ixj] = a; }
            }
            __syncthreads();
        }
    }

    // ---- pass-2 flips: top-nflip2 candidates ----
    if (tid < nflip2) {
        unsigned long long kk = s_key[tid];
        int idx = 0x3FFF - (int)((kk >> 8) & 0x3FFFull);
        int val = (int)(kk & 0xFFull) - 64;
        s_r[idx] = (signed char)val;
    }
    __syncthreads();

    // ---- clip + dequantize ----
    float* __restrict__ orow = out + (size_t)row * ROWLEN;
#pragma unroll
    for (int i = tid; i < ROWLEN; i += NTHREADS) {
        float rr = (float)s_r[i];
        rr = fminf(7.f, fmaxf(-8.f, rr));
        orow[i] = (rr + zp) / scale;
    }
}

extern "C" void kernel_launch(void* const* d_in, const int* in_sizes, int n_in,
                              void* d_out, int out_size)
{
    const float* w = (const float*)d_in[0];
    float* out = (float*)d_out;
    squant_kernel<<<NROWS, NTHREADS, SMEM_BYTES>>>(w, out);
}

// round 2
// speedup vs baseline: 2.0006x; 2.0006x over previous
#include <cuda_runtime.h>
#include <cstdint>
#include <cfloat>

// SQuant 4-bit adaptive rounding, fused single kernel (round 2).
// One block per output channel (row of 9216 fp32).
// Pass 2 selection: register-resident keys + __syncthreads_count binary
// search for the k-th largest priority (replaces shared-memory bitonic sort).

#define NROWS    1024
#define ROWLEN   9216
#define NV4      2304      // ROWLEN/4
#define NTHREADS 1024

// shared layout (dynamic):
//   [0,     36864)  s_w   : row of 9216 floats
//   [36864, 46080)  s_r   : 9216 int8 rounded values
//   [46080, 46336)  s_red : 64 floats reduction scratch (aliased as int for tie path)
//   [46336, 46352)  s_bc  : broadcast (scale, zp, e2)
#define SMEM_BYTES 46352

__device__ __forceinline__ float warpSum(float v) {
#pragma unroll
    for (int o = 16; o; o >>= 1) v += __shfl_xor_sync(0xffffffffu, v, o);
    return v;
}
__device__ __forceinline__ float warpMaxR(float v) {
#pragma unroll
    for (int o = 16; o; o >>= 1) v = fmaxf(v, __shfl_xor_sync(0xffffffffu, v, o));
    return v;
}
__device__ __forceinline__ float warpMinR(float v) {
#pragma unroll
    for (int o = 16; o; o >>= 1) v = fminf(v, __shfl_xor_sync(0xffffffffu, v, o));
    return v;
}

__global__ void __launch_bounds__(NTHREADS, 1)
squant_kernel(const float* __restrict__ w, float* __restrict__ out)
{
    extern __shared__ unsigned char smem[];
    float*       s_w   = (float*)smem;                       // 36864 B
    signed char* s_r   = (signed char*)(smem + 36864);       // 9216 B
    float*       s_red = (float*)(smem + 46080);             // 64 floats
    int*         s_cnt = (int*)(smem + 46080);               // aliases s_red (later phase)
    float*       s_bc  = (float*)(smem + 46336);

    const int tid  = threadIdx.x;
    const int lane = tid & 31;
    const int wid  = tid >> 5;

    const float4* __restrict__ w4 = (const float4*)(w + (size_t)blockIdx.x * ROWLEN);
    float4* sw4 = (float4*)s_w;

    // ---- vectorized load + min/max ----
    float vmax = -FLT_MAX, vmin = FLT_MAX;
    for (int i = tid; i < NV4; i += NTHREADS) {
        float4 v = w4[i];
        sw4[i] = v;
        vmax = fmaxf(vmax, fmaxf(fmaxf(v.x, v.y), fmaxf(v.z, v.w)));
        vmin = fminf(vmin, fminf(fminf(v.x, v.y), fminf(v.z, v.w)));
    }
    vmax = warpMaxR(vmax);
    vmin = warpMinR(vmin);
    if (lane == 0) { s_red[wid] = vmax; s_red[32 + wid] = vmin; }
    __syncthreads();
    if (wid == 0) {
        float m = warpMaxR(s_red[lane]);
        float n = warpMinR(s_red[32 + lane]);
        if (lane == 0) {
            float sc = 15.0f / fmaxf(m - n, 1e-8f);
            s_bc[0] = sc;
            s_bc[1] = rintf(sc * n) + 8.0f;   // zero point
        }
    }
    __syncthreads();
    const float scale = s_bc[0];
    const float zp    = s_bc[1];

    // ---- pass 1: SQuant-K over this thread's 9-element kernel group ----
    const int base = tid * 9;
    float rv[9], ev[9];
    unsigned cu = 0, cd = 0;
    float e = 0.f;
#pragma unroll
    for (int j = 0; j < 9; j++) {
        float qq = fmaf(scale, s_w[base + j], -zp);
        float rr = rintf(qq);
        float ee = rr - qq;
        rv[j] = rr; ev[j] = ee;
        if (ee < 0.f && qq <  7.f) cu |= (1u << j);
        if (ee > 0.f && qq > -8.f) cd |= (1u << j);
        e += ee;
    }
    const bool is_up = (e < 0.f);
    int nflip = (int)rintf(fabsf(e));   // mathematically <= 5
    if (nflip > 8) nflip = 8;
    const unsigned cand = is_up ? cu : cd;

    // priority bits (monotone uint for |err|, 0 for non-candidates)
    unsigned pu[9];
#pragma unroll
    for (int j = 0; j < 9; j++)
        pu[j] = ((cand >> j) & 1u) ? (__float_as_uint(ev[j]) & 0x7fffffffu) : 0u;

    // rank_j = #{i : pri_i > pri_j or (pri_i == pri_j and i < j)}  (stable desc order)
    int rk[9];
#pragma unroll
    for (int j = 0; j < 9; j++) {
        int r = 0;
#pragma unroll
        for (int i = 0; i < 9; i++) {
            if (i < j)      r += (pu[i] >= pu[j]);
            else if (i > j) r += (pu[i] >  pu[j]);
        }
        rk[j] = r;
    }

    // apply flips (rank < nflip), capture boundary elements ni (rank==nflip)
    // and li (rank==nflip-1), accumulate residual error
    const float dir = is_up ? 1.f : -1.f;
    float er = 0.f;
    float evNi = 0.f, rvNi = 0.f, evLi = 0.f, rvLi = 0.f;
    int ni = 0, li = 0;
#pragma unroll
    for (int j = 0; j < 9; j++) {
        bool c = (cand >> j) & 1u;
        float nr = rv[j], ne = ev[j];
        if (rk[j] < nflip) {
            if (c) { nr += dir; ne += dir; }
            else   { ne = 0.f; }            // flipping a non-candidate zeroes err
        }
        er += ne;
        s_r[base + j] = (signed char)__float2int_rn(nr);
        if (rk[j] == nflip)     { evNi = ev[j]; rvNi = rv[j]; ni = j; }
        if (rk[j] == nflip - 1) { evLi = ev[j]; rvLi = rv[j]; li = j; }
    }

    const bool hasL   = (nflip > 0);
    const bool candNi = (cand >> ni) & 1u;
    const bool candLi = hasL && ((cand >> li) & 1u);

    const float priNi = candNi ? fabsf(evNi) : 0.f;                 // flip-one-more
    const int   valNi = (int)rvNi + (candNi ? (is_up ? 1 : -1) : 0);
    float priLi; int valLi, idxLi;
    if (hasL) {                                                     // revert-last
        priLi = 1.f - (candLi ? fabsf(evLi) : 0.f);
        valLi = (int)rvLi;                                          // pre-flip value
        idxLi = base + li;
    } else {                                                        // pri-0 dummy
        priLi = 0.f; valLi = valNi; idxLi = base + ni;
    }

    float upP, dnP; int upI, dnI, upV, dnV;
    if (is_up) { upP = priNi; upI = base + ni; upV = valNi;
                 dnP = priLi; dnI = idxLi;     dnV = valLi; }
    else       { dnP = priNi; dnI = base + ni; dnV = valNi;
                 upP = priLi; upI = idxLi;     upV = valLi; }

    // ---- row residual-error reduction -> pass-2 flip budget ----
    float s = warpSum(er);
    if (lane == 0) s_red[wid] = s;
    __syncthreads();
    if (wid == 0) {
        float t2 = warpSum(s_red[lane]);
        if (lane == 0) s_bc[2] = t2;
    }
    __syncthreads();
    const float e2  = s_bc[2];
    const bool  up2 = (e2 < 0.f);
    int k = (int)rintf(fabsf(e2));
    if (k > NTHREADS) k = NTHREADS;

    // this thread's pass-2 candidate (chosen direction), register-resident
    const float    P = up2 ? upP : dnP;
    const int      I = up2 ? upI : dnI;
    const int      V = up2 ? upV : dnV;
    const unsigned myU = __float_as_uint(P);   // P >= 0 -> bits are monotone

    if (k > 0) {
        // binary search for k-th largest priority via hardware barrier+count.
        // invariant: cnt(U >= lo) >= k,  cnt(U >= hi+1) < k
        unsigned lo = 0u, hi = 0x3F800000u;    // pri in [0, 1]
        bool early = false;
        while (lo < hi) {
            unsigned mid = (lo + hi + 1) >> 1;
            int c = __syncthreads_count(myU >= mid);
            if (c == k) { lo = mid; early = true; break; }   // clean separation
            if (c > k) lo = mid; else hi = mid - 1;
        }
        if (early) {
            if (myU >= lo) s_r[I] = (signed char)V;
        } else {
            // Uk = lo is the k-th largest value; resolve ties by ascending index
            const unsigned Uk = lo;
            int cGT = __syncthreads_count(myU > Uk);
            int rem = k - cGT;                  // >= 1 here
            bool eq = (myU == Uk);
            unsigned ball = __ballot_sync(0xffffffffu, eq);
            int lanePre = __popc(ball & ((1u << lane) - 1u));
            if (lane == 0) s_cnt[wid] = __popc(ball);
            __syncthreads();
            int pre = 0;
            for (int wdx = 0; wdx < wid; wdx++) pre += s_cnt[wdx];
            if (myU > Uk || (eq && (pre + lanePre) < rem))
                s_r[I] = (signed char)V;
        }
    }
    __syncthreads();

    // ---- clip + dequantize (vectorized, reciprocal multiply) ----
    const float inv = 1.0f / scale;
    float4* __restrict__ orow4 = (float4*)(out + (size_t)blockIdx.x * ROWLEN);
    const int* s_ri = (const int*)s_r;
    for (int i = tid; i < NV4; i += NTHREADS) {
        int p = s_ri[i];
        int b0 = (int)(signed char)(p);
        int b1 = (int)(signed char)(p >> 8);
        int b2 = (int)(signed char)(p >> 16);
        int b3 = (int)(signed char)(p >> 24);
        b0 = min(7, max(-8, b0));
        b1 = min(7, max(-8, b1));
        b2 = min(7, max(-8, b2));
        b3 = min(7, max(-8, b3));
        float4 o;
        o.x = ((float)b0 + zp) * inv;
        o.y = ((float)b1 + zp) * inv;
        o.z = ((float)b2 + zp) * inv;
        o.w = ((float)b3 + zp) * inv;
        orow4[i] = o;
    }
}

extern "C" void kernel_launch(void* const* d_in, const int* in_sizes, int n_in,
                              void* d_out, int out_size)
{
    const float* w = (const float*)d_in[0];
    float* out = (float*)d_out;
    squant_kernel<<<NROWS, NTHREADS, SMEM_BYTES>>>(w, out);
}

// round 3
// speedup vs baseline: 2.8935x; 1.4463x over previous
#include <cuda_runtime.h>
#include <cstdint>
#include <cfloat>

// SQuant 4-bit adaptive rounding, fused single kernel (round 3).
// 256 threads/block, 4 kernel-groups per thread, 4 blocks resident per SM
// (independent barrier domains hide BAR drain). One block per output channel.

#define NROWS   1024
#define ROWLEN  9216
#define NV4     2304
#define NT      256
#define NGROUP  4
#define NWARP   8

// shared layout (dynamic):
//   [0,     36864) s_w    : row of 9216 floats
//   [36864, 46080) s_r    : 9216 int8 rounded values
//   [46080, 46144) s_red  : 16 floats (per-warp max[8], min[8])
//   [46144, 46176) s_sum  : 8 floats  (per-warp residual-error sums)
//   [46176, 46240) s_cnt  : 2 x 8 ints (parity double-buffered counts)
#define SMEM_BYTES 46240

__device__ __forceinline__ float warpSum(float v) {
#pragma unroll
    for (int o = 16; o; o >>= 1) v += __shfl_xor_sync(0xffffffffu, v, o);
    return v;
}
__device__ __forceinline__ float warpMaxR(float v) {
#pragma unroll
    for (int o = 16; o; o >>= 1) v = fmaxf(v, __shfl_xor_sync(0xffffffffu, v, o));
    return v;
}
__device__ __forceinline__ float warpMinR(float v) {
#pragma unroll
    for (int o = 16; o; o >>= 1) v = fminf(v, __shfl_xor_sync(0xffffffffu, v, o));
    return v;
}

// block-wide count of c_local (0..4 per thread) in ONE barrier.
// parity alternates per call (double-buffered scratch).
__device__ __forceinline__ int blockCount(int c_local, int* s_cnt, int parity,
                                          int wid, int lane) {
    int cw = __reduce_add_sync(0xffffffffu, c_local);
    if (lane == 0) s_cnt[parity * NWARP + wid] = cw;
    __syncthreads();
    int t = 0;
#pragma unroll
    for (int i = 0; i < NWARP; i++) t += s_cnt[parity * NWARP + i];
    return t;
}

__global__ void __launch_bounds__(NT, 4)
squant_kernel(const float* __restrict__ w, float* __restrict__ out)
{
    extern __shared__ unsigned char smem[];
    float*       s_w   = (float*)smem;
    signed char* s_r   = (signed char*)(smem + 36864);
    float*       s_red = (float*)(smem + 46080);
    float*       s_sum = (float*)(smem + 46144);
    int*         s_cnt = (int*)(smem + 46176);

    const int tid  = threadIdx.x;
    const int lane = tid & 31;
    const int wid  = tid >> 5;

    const float4* __restrict__ w4 = (const float4*)(w + (size_t)blockIdx.x * ROWLEN);
    float4* sw4 = (float4*)s_w;

    // ---- vectorized load + min/max (1 barrier total) ----
    float vmax = -FLT_MAX, vmin = FLT_MAX;
#pragma unroll
    for (int i = tid; i < NV4; i += NT) {
        float4 v = w4[i];
        sw4[i] = v;
        vmax = fmaxf(vmax, fmaxf(fmaxf(v.x, v.y), fmaxf(v.z, v.w)));
        vmin = fminf(vmin, fminf(fminf(v.x, v.y), fminf(v.z, v.w)));
    }
    vmax = warpMaxR(vmax);
    vmin = warpMinR(vmin);
    if (lane == 0) { s_red[wid] = vmax; s_red[NWARP + wid] = vmin; }
    __syncthreads();                       // also publishes s_w
    float m = s_red[0], n = s_red[NWARP];
#pragma unroll
    for (int i = 1; i < NWARP; i++) {
        m = fmaxf(m, s_red[i]);
        n = fminf(n, s_red[NWARP + i]);
    }
    const float scale = 15.0f / fmaxf(m - n, 1e-8f);
    const float zp    = rintf(scale * n) + 8.0f;

    // ---- pass 1: SQuant-K, 4 groups per thread ----
    float    Pup[NGROUP], Pdn[NGROUP];
    unsigned IVup[NGROUP], IVdn[NGROUP];   // (elem_idx << 8) | (val + 32)
    float er_tot = 0.f;

#pragma unroll
    for (int g = 0; g < NGROUP; g++) {
        const int base = (g * NT + tid) * 9;
        float rv[9], ev[9];
        unsigned cu = 0, cd = 0;
        float e = 0.f;
#pragma unroll
        for (int j = 0; j < 9; j++) {
            float qq = fmaf(scale, s_w[base + j], -zp);
            float rr = rintf(qq);
            float ee = rr - qq;
            rv[j] = rr; ev[j] = ee;
            if (ee < 0.f && qq <  7.f) cu |= (1u << j);
            if (ee > 0.f && qq > -8.f) cd |= (1u << j);
            e += ee;
        }
        const bool is_up = (e < 0.f);
        int nflip = (int)rintf(fabsf(e));   // mathematically <= 5
        if (nflip > 8) nflip = 8;
        const unsigned cand = is_up ? cu : cd;

        unsigned pu[9];
#pragma unroll
        for (int j = 0; j < 9; j++)
            pu[j] = ((cand >> j) & 1u) ? (__float_as_uint(ev[j]) & 0x7fffffffu) : 0u;

        // stable descending ranks via shared pairwise compares (36 compares)
        int rk[9];
#pragma unroll
        for (int j = 0; j < 9; j++) rk[j] = 0;
#pragma unroll
        for (int j = 1; j < 9; j++)
#pragma unroll
            for (int i = 0; i < j; i++) {
                bool c = pu[i] >= pu[j];
                rk[j] += c ? 1 : 0;
                rk[i] += c ? 0 : 1;
            }

        const float dir = is_up ? 1.f : -1.f;
        float er = 0.f;
        float evNi = 0.f, rvNi = 0.f, evLi = 0.f, rvLi = 0.f;
        int ni = 0, li = 0;
#pragma unroll
        for (int j = 0; j < 9; j++) {
            bool c = (cand >> j) & 1u;
            float nr = rv[j], ne = ev[j];
            if (rk[j] < nflip) {
                if (c) { nr += dir; ne += dir; }
                else   { ne = 0.f; }
            }
            er += ne;
            s_r[base + j] = (signed char)__float2int_rn(nr);
            if (rk[j] == nflip)     { evNi = ev[j]; rvNi = rv[j]; ni = j; }
            if (rk[j] == nflip - 1) { evLi = ev[j]; rvLi = rv[j]; li = j; }
        }
        er_tot += er;

        const bool hasL   = (nflip > 0);
        const bool candNi = (cand >> ni) & 1u;
        const bool candLi = hasL && ((cand >> li) & 1u);

        const float priNi = candNi ? fabsf(evNi) : 0.f;               // flip-one-more
        const int   valNi = (int)rvNi + (candNi ? (is_up ? 1 : -1) : 0);
        float priLi; int valLi, idxLi;
        if (hasL) {                                                   // revert-last
            priLi = 1.f - (candLi ? fabsf(evLi) : 0.f);
            valLi = (int)rvLi;
            idxLi = base + li;
        } else {
            priLi = 0.f; valLi = valNi; idxLi = base + ni;
        }

        if (is_up) {
            Pup[g] = priNi; IVup[g] = ((unsigned)(base + ni) << 8) | (unsigned)(valNi + 32);
            Pdn[g] = priLi; IVdn[g] = ((unsigned)idxLi       << 8) | (unsigned)(valLi + 32);
        } else {
            Pdn[g] = priNi; IVdn[g] = ((unsigned)(base + ni) << 8) | (unsigned)(valNi + 32);
            Pup[g] = priLi; IVup[g] = ((unsigned)idxLi       << 8) | (unsigned)(valLi + 32);
        }
    }

    // ---- row residual-error reduction (1 barrier) ----
    {
        float s = warpSum(er_tot);
        if (lane == 0) s_sum[wid] = s;
    }
    __syncthreads();
    float e2 = s_sum[0];
#pragma unroll
    for (int i = 1; i < NWARP; i++) e2 += s_sum[i];

    const bool up2 = (e2 < 0.f);
    int k = (int)rintf(fabsf(e2));
    if (k > NT * NGROUP) k = NT * NGROUP;

    unsigned U[NGROUP], IV[NGROUP];
#pragma unroll
    for (int g = 0; g < NGROUP; g++) {
        U[g]  = __float_as_uint(up2 ? Pup[g] : Pdn[g]);   // P >= 0 -> bits monotone
        IV[g] = up2 ? IVup[g] : IVdn[g];
    }

    // ---- pass-2 selection: value-guided bisection for k-th largest ----
    if (k > 0) {
        int parity = 0;
        unsigned lo = 0u, hi = 0x3F800000u;   // invariant: cnt(>=lo)>=k, cnt(>=hi+1)<k
        bool found = false;
        unsigned thr = 0;
        while (lo < hi) {
            float midf = 0.5f * (__uint_as_float(lo) + __uint_as_float(hi));
            unsigned mid = __float_as_uint(midf);
            if (mid <= lo) mid = lo + 1;
            else if (mid > hi) mid = hi;
            int cl = (U[0] >= mid) + (U[1] >= mid) + (U[2] >= mid) + (U[3] >= mid);
            int c = blockCount(cl, s_cnt, parity, wid, lane); parity ^= 1;
            if (c == k) { thr = mid; found = true; break; }
            if (c > k) lo = mid; else hi = mid - 1;
        }
        if (found) {
#pragma unroll
            for (int g = 0; g < NGROUP; g++)
                if (U[g] >= thr)
                    s_r[IV[g] >> 8] = (signed char)((int)(IV[g] & 0xFFu) - 32);
        } else {
            // exact ties at the k-th priority: resolve by ascending element index
            const unsigned Uk = lo;
            int clg = (U[0] > Uk) + (U[1] > Uk) + (U[2] > Uk) + (U[3] > Uk);
            int cGT = blockCount(clg, s_cnt, parity, wid, lane); parity ^= 1;
            int rem = k - cGT;                  // >= 1
            int ilo = 0, ihi = ROWLEN, mI = ROWLEN;
            for (;;) {
                mI = (ilo + ihi + 1) >> 1;
                int ct = ((U[0] == Uk) && (int)(IV[0] >> 8) < mI)
                       + ((U[1] == Uk) && (int)(IV[1] >> 8) < mI)
                       + ((U[2] == Uk) && (int)(IV[2] >> 8) < mI)
                       + ((U[3] == Uk) && (int)(IV[3] >> 8) < mI);
                int c = blockCount(ct, s_cnt, parity, wid, lane); parity ^= 1;
                if (c == rem) break;            // unique indices -> always reachable
                if (c < rem) ilo = mI; else ihi = mI - 1;
            }
#pragma unroll
            for (int g = 0; g < NGROUP; g++)
                if (U[g] > Uk || (U[g] == Uk && (int)(IV[g] >> 8) < mI))
                    s_r[IV[g] >> 8] = (signed char)((int)(IV[g] & 0xFFu) - 32);
        }
    }
    __syncthreads();

    // ---- clip + dequantize (packed clip, reciprocal multiply) ----
    const float inv   = 1.0f / scale;
    const float zpinv = zp * inv;
    float4* __restrict__ orow4 = (float4*)(out + (size_t)blockIdx.x * ROWLEN);
    const int* s_ri = (const int*)s_r;
#pragma unroll
    for (int i = tid; i < NV4; i += NT) {
        int p = s_ri[i];
        p = __vmins4(__vmaxs4(p, 0xF8F8F8F8), 0x07070707);   // clip each byte to [-8,7]
        float4 o;
        o.x = fmaf((float)(int)(signed char)(p),       inv, zpinv);
        o.y = fmaf((float)(int)(signed char)(p >> 8),  inv, zpinv);
        o.z = fmaf((float)(int)(signed char)(p >> 16), inv, zpinv);
        o.w = fmaf((float)(int)(signed char)(p >> 24), inv, zpinv);
        orow4[i] = o;
    }
}

extern "C" void kernel_launch(void* const* d_in, const int* in_sizes, int n_in,
                              void* d_out, int out_size)
{
    const float* w = (const float*)d_in[0];
    float* out = (float*)d_out;
    squant_kernel<<<NROWS, NT, SMEM_BYTES>>>(w, out);
}